// round 6
// baseline (speedup 1.0000x reference)
#include <cuda_runtime.h>
#include <cuda_bf16.h>

#define BB 32
#define CC 384
#define TT 512
#define MAX_FRAMES 6656   // TT * 13

// out layout in d_out (float):
//   [0, BB*CC*MAX_FRAMES)                      : out (b, c, pos)
//   [+0, +BB*MAX_FRAMES)                       : pitch (b, pos)
//   [+0, +BB)                                  : frame_lengths (as float value)
#define OUT_ELEMS   ((size_t)BB * CC * MAX_FRAMES)
#define PITCH_OFF   OUT_ELEMS
#define LEN_OFF     (OUT_ELEMS + (size_t)BB * MAX_FRAMES)

// scratch (allocation-free rule: __device__ globals)
__device__ int g_tok[BB * MAX_FRAMES];
__device__ int g_len[BB];

// ---------------------------------------------------------------------------
// Kernel A: per-batch repeat counts, inclusive scan, searchsorted -> tok,
// pitch output, frame_lengths output.
// grid = BB blocks, 512 threads.
// ---------------------------------------------------------------------------
__global__ void __launch_bounds__(TT) scan_kernel(
    const float* __restrict__ duration,
    const float* __restrict__ notepitch,
    float* __restrict__ out)
{
    const int b = blockIdx.x;
    const int t = threadIdx.x;

    __shared__ int   cum[TT];
    __shared__ float pitch_s[TT];

    // exact replication of _repeat_counts in fp32 (no FMA contraction)
    const float d  = duration[b * TT + t];
    const float fr = __fmul_rn(44100.0f, d);
    const float fm = __fsub_rn(fr, 1024.0f);
    float rr;
    if (fm > 0.0f) {
        rr = fmaxf(__fmul_rn(fm, (1.0f / 256.0f)), 1.0f);
    } else {
        rr = (d == 0.0f) ? 0.0f : 1.0f;
    }
    const int r = (int)rr;  // astype(int32): truncation toward zero (rr >= 0)

    pitch_s[t] = notepitch[b * TT + t];
    cum[t] = r;
    __syncthreads();

    // Hillis-Steele inclusive scan over 512 elements
    #pragma unroll
    for (int off = 1; off < TT; off <<= 1) {
        int v = cum[t] + ((t >= off) ? cum[t - off] : 0);
        __syncthreads();
        cum[t] = v;
        __syncthreads();
    }

    const int L = cum[TT - 1];
    if (t == 0) {
        g_len[b] = L;
        out[LEN_OFF + b] = (float)L;   // frame_lengths as float value
    }

    // searchsorted(cum, pos, side='right') for all MAX_FRAMES positions.
    // Answer range is [0, 512] (513 candidates) -> needs 10 halving steps.
    int* tok_row = g_tok + b * MAX_FRAMES;
    float* pitch_out = out + PITCH_OFF + (size_t)b * MAX_FRAMES;

    for (int pos = t; pos < MAX_FRAMES; pos += TT) {
        int lo = 0, hi = TT;
        #pragma unroll
        for (int step = 0; step < 10; step++) {   // ceil(log2(513)) = 10
            if (lo < hi) {
                int mid = (lo + hi) >> 1;
                if (cum[mid] <= pos) lo = mid + 1; else hi = mid;
            }
        }
        int tok = lo < (TT - 1) ? lo : (TT - 1);
        tok_row[pos] = tok;
        float p = 0.0f;
        if (pos < L) {
            p = (float)(int)pitch_s[tok];  // astype(int32).astype(float32)
        }
        pitch_out[pos] = p;
    }
}

// ---------------------------------------------------------------------------
// Kernel B: expand x along tok, masked by L, vectorized float4 writes.
// grid = BB*CC blocks, 256 threads; x row cached in SMEM.
// ---------------------------------------------------------------------------
__global__ void __launch_bounds__(256) expand_kernel(
    const float* __restrict__ x,
    float* __restrict__ out)
{
    const int bc  = blockIdx.x;       // b * CC + c
    const int b   = bc / CC;
    const int tid = threadIdx.x;

    __shared__ float xs[TT];
    __shared__ int   L_s;

    const float* xrow = x + (size_t)bc * TT;
    xs[tid]       = xrow[tid];
    xs[tid + 256] = xrow[tid + 256];
    if (tid == 0) L_s = g_len[b];
    __syncthreads();

    const int L = L_s;
    const int4*  tokv = (const int4*)(g_tok + b * MAX_FRAMES);
    float4* outv = (float4*)(out + (size_t)bc * MAX_FRAMES);

    #pragma unroll 4
    for (int i = tid; i < MAX_FRAMES / 4; i += 256) {
        const int pos = i << 2;
        float4 v;
        if (pos + 3 < L) {
            int4 tk = tokv[i];
            v.x = xs[tk.x]; v.y = xs[tk.y]; v.z = xs[tk.z]; v.w = xs[tk.w];
        } else if (pos >= L) {
            v.x = 0.0f; v.y = 0.0f; v.z = 0.0f; v.w = 0.0f;
        } else {
            int4 tk = tokv[i];
            v.x = (pos + 0 < L) ? xs[tk.x] : 0.0f;
            v.y = (pos + 1 < L) ? xs[tk.y] : 0.0f;
            v.z = (pos + 2 < L) ? xs[tk.z] : 0.0f;
            v.w = (pos + 3 < L) ? xs[tk.w] : 0.0f;
        }
        outv[i] = v;
    }
}

extern "C" void kernel_launch(void* const* d_in, const int* in_sizes, int n_in,
                              void* d_out, int out_size)
{
    const float* x         = (const float*)d_in[0];
    const float* notepitch = (const float*)d_in[1];
    const float* duration  = (const float*)d_in[2];
    // d_in[3] = x_lengths (unused by the reference)
    float* out = (float*)d_out;

    scan_kernel<<<BB, TT>>>(duration, notepitch, out);
    expand_kernel<<<BB * CC, 256>>>(x, out);
}

// round 7
// speedup vs baseline: 1.0516x; 1.0516x over previous
#include <cuda_runtime.h>
#include <cuda_bf16.h>

#define BB 32
#define CC 384
#define TT 512
#define MAX_FRAMES 6656   // TT * 13 ; 13 * 512
#define G 4               // channels per expand block
#define CGROUPS (CC / G)  // 96

// out layout in d_out (float):
//   [0, BB*CC*MAX_FRAMES)            : out (b, c, pos)
//   [+0, +BB*MAX_FRAMES)             : pitch (b, pos)
//   [+0, +BB)                        : frame_lengths (as float value)
#define OUT_ELEMS   ((size_t)BB * CC * MAX_FRAMES)
#define PITCH_OFF   OUT_ELEMS
#define LEN_OFF     (OUT_ELEMS + (size_t)BB * MAX_FRAMES)

// scratch (allocation-free rule: __device__ globals)
__device__ __align__(16) unsigned short g_tok16[BB * MAX_FRAMES];
__device__ int g_len[BB];

// ---------------------------------------------------------------------------
// Kernel A (fused scan + tok + pitch): grid (13, 32), 512 threads.
// Each block recomputes the per-batch cumsum via shfl-scan (cheap), then
// searchsorted for its 512 positions; writes g_tok16 (u16), pitch, lengths.
// ---------------------------------------------------------------------------
__global__ void __launch_bounds__(TT) tok_kernel(
    const float* __restrict__ duration,
    const float* __restrict__ notepitch,
    float* __restrict__ out)
{
    const int b = blockIdx.y;
    const int j = blockIdx.x;          // pos chunk 0..12
    const int t = threadIdx.x;
    const int lane = t & 31, wid = t >> 5;

    __shared__ int   cum[TT];
    __shared__ float pitch_s[TT];
    __shared__ int   wsum[16];

    // exact replication of _repeat_counts in fp32 (no FMA contraction)
    const float d  = duration[b * TT + t];
    const float fr = __fmul_rn(44100.0f, d);
    const float fm = __fsub_rn(fr, 1024.0f);
    float rr;
    if (fm > 0.0f) rr = fmaxf(__fmul_rn(fm, (1.0f / 256.0f)), 1.0f);
    else           rr = (d == 0.0f) ? 0.0f : 1.0f;
    int v = (int)rr;   // truncation toward zero (rr >= 0)

    pitch_s[t] = notepitch[b * TT + t];

    // inclusive scan: warp shfl-scan + warp-sum scan
    #pragma unroll
    for (int o = 1; o < 32; o <<= 1) {
        int n = __shfl_up_sync(0xFFFFFFFFu, v, o);
        if (lane >= o) v += n;
    }
    if (lane == 31) wsum[wid] = v;
    __syncthreads();
    if (wid == 0) {
        int s = 0;
        if (lane < 16) s = wsum[lane];
        #pragma unroll
        for (int o = 1; o < 16; o <<= 1) {
            int n = __shfl_up_sync(0xFFFFFFFFu, s, o);
            if (lane >= o) s += n;
        }
        if (lane < 16) wsum[lane] = s;
    }
    __syncthreads();
    const int base = (wid > 0) ? wsum[wid - 1] : 0;
    cum[t] = v + base;
    __syncthreads();

    const int L = cum[TT - 1];
    if (j == 0 && t == 0) {
        g_len[b] = L;
        out[LEN_OFF + b] = (float)L;
    }

    // searchsorted(cum, pos, side='right'); answer in [0,512] -> 10 steps
    const int pos = j * TT + t;
    int lo = 0, hi = TT;
    #pragma unroll
    for (int s = 0; s < 10; s++) {
        if (lo < hi) {
            int mid = (lo + hi) >> 1;
            if (cum[mid] <= pos) lo = mid + 1; else hi = mid;
        }
    }
    const int tok = lo < (TT - 1) ? lo : (TT - 1);
    g_tok16[(size_t)b * MAX_FRAMES + pos] = (unsigned short)tok;
    out[PITCH_OFF + (size_t)b * MAX_FRAMES + pos] =
        (pos < L) ? (float)(int)pitch_s[tok] : 0.0f;
}

// ---------------------------------------------------------------------------
// Kernel B: expand. grid (96, 32) = (cgroup, b), 256 threads.
// One tok uint2 load (4 positions, u16) feeds G=4 float4 stores; x rows for
// the 4 channels are SMEM-resident.
// ---------------------------------------------------------------------------
__global__ void __launch_bounds__(256) expand_kernel(
    const float* __restrict__ x,
    float* __restrict__ out)
{
    const int cg  = blockIdx.x;
    const int b   = blockIdx.y;
    const int tid = threadIdx.x;

    __shared__ float xs[G * TT];   // 8 KB
    __shared__ int   L_s;

    const float4* xsrc = (const float4*)(x + ((size_t)b * CC + (size_t)cg * G) * TT);
    float4* xdst = (float4*)xs;
    #pragma unroll
    for (int i = tid; i < G * TT / 4; i += 256) xdst[i] = xsrc[i];
    if (tid == 0) L_s = g_len[b];
    __syncthreads();

    const int L = L_s;
    const uint2* tokv = (const uint2*)(g_tok16 + (size_t)b * MAX_FRAMES);
    float* outbase = out + ((size_t)b * CC + (size_t)cg * G) * MAX_FRAMES;

    for (int i = tid; i < MAX_FRAMES / 4; i += 256) {   // 1664 float4 slots
        const int pos = i << 2;
        const uint2 tw = tokv[i];
        const int t0 = tw.x & 0xFFFF, t1 = tw.x >> 16;
        const int t2 = tw.y & 0xFFFF, t3 = tw.y >> 16;

        if (pos + 3 < L) {
            #pragma unroll
            for (int c = 0; c < G; c++) {
                const float* xc = xs + c * TT;
                float4 v = make_float4(xc[t0], xc[t1], xc[t2], xc[t3]);
                ((float4*)(outbase + (size_t)c * MAX_FRAMES))[i] = v;
            }
        } else if (pos >= L) {
            const float4 z = make_float4(0.0f, 0.0f, 0.0f, 0.0f);
            #pragma unroll
            for (int c = 0; c < G; c++)
                ((float4*)(outbase + (size_t)c * MAX_FRAMES))[i] = z;
        } else {
            #pragma unroll
            for (int c = 0; c < G; c++) {
                const float* xc = xs + c * TT;
                float4 v;
                v.x = (pos + 0 < L) ? xc[t0] : 0.0f;
                v.y = (pos + 1 < L) ? xc[t1] : 0.0f;
                v.z = (pos + 2 < L) ? xc[t2] : 0.0f;
                v.w = (pos + 3 < L) ? xc[t3] : 0.0f;
                ((float4*)(outbase + (size_t)c * MAX_FRAMES))[i] = v;
            }
        }
    }
}

extern "C" void kernel_launch(void* const* d_in, const int* in_sizes, int n_in,
                              void* d_out, int out_size)
{
    const float* x         = (const float*)d_in[0];
    const float* notepitch = (const float*)d_in[1];
    const float* duration  = (const float*)d_in[2];
    // d_in[3] = x_lengths (unused by the reference)
    float* out = (float*)d_out;

    tok_kernel<<<dim3(MAX_FRAMES / TT, BB), TT>>>(duration, notepitch, out);
    expand_kernel<<<dim3(CGROUPS, BB), 256>>>(x, out);
}

// round 9
// speedup vs baseline: 1.0835x; 1.0303x over previous
#include <cuda_runtime.h>
#include <cuda_bf16.h>
#include <cstdint>

#define BB 32
#define CC 384
#define TT 512
#define MAX_FRAMES 6656   // TT * 13
#define G 4               // channels per expand block
#define CGROUPS (CC / G)  // 96

// out layout in d_out (float):
//   [0, BB*CC*MAX_FRAMES)            : out (b, c, pos)
//   [+0, +BB*MAX_FRAMES)             : pitch (b, pos)
//   [+0, +BB)                        : frame_lengths (as float value)
#define OUT_ELEMS   ((size_t)BB * CC * MAX_FRAMES)
#define PITCH_OFF   OUT_ELEMS
#define LEN_OFF     (OUT_ELEMS + (size_t)BB * MAX_FRAMES)

// ---------------------------------------------------------------------------
// Single fused kernel. grid = (CGROUPS+1, BB), 256 threads.
//   cg <  CGROUPS : expand 4 channels of x
//   cg == CGROUPS : write pitch + frame_lengths
// Every block independently recomputes the per-batch repeat counts, an
// inclusive scan (registers + shfl), and scatter-fills the tok map in SMEM.
// ---------------------------------------------------------------------------
__global__ void __launch_bounds__(256) fused_kernel(
    const float* __restrict__ x,
    const float* __restrict__ notepitch,
    const float* __restrict__ duration,
    float* __restrict__ out)
{
    const int cg  = blockIdx.x;
    const int b   = blockIdx.y;
    const int tid = threadIdx.x;
    const int lane = tid & 31, wid = tid >> 5;

    __shared__ float xs[G * TT];                     // 8 KB (x rows OR pitch row)
    __shared__ unsigned short tok_s[MAX_FRAMES];     // 13 KB
    __shared__ int wsum[8];
    __shared__ int L_s;

    // ---- repeat counts for elements e0=2*tid, e1=2*tid+1 (exact fp32) ----
    const float2 d2 = ((const float2*)(duration + b * TT))[tid];
    int r0, r1;
    {
        const float fm = __fsub_rn(__fmul_rn(44100.0f, d2.x), 1024.0f);
        float rr;
        if (fm > 0.0f) rr = fmaxf(__fmul_rn(fm, (1.0f / 256.0f)), 1.0f);
        else           rr = (d2.x == 0.0f) ? 0.0f : 1.0f;
        r0 = (int)rr;
    }
    {
        const float fm = __fsub_rn(__fmul_rn(44100.0f, d2.y), 1024.0f);
        float rr;
        if (fm > 0.0f) rr = fmaxf(__fmul_rn(fm, (1.0f / 256.0f)), 1.0f);
        else           rr = (d2.y == 0.0f) ? 0.0f : 1.0f;
        r1 = (int)rr;
    }

    // ---- init tok map to 511 (searchsorted clamp value for pos >= L) ----
    {
        unsigned int* tw = (unsigned int*)tok_s;
        #pragma unroll
        for (int i = tid; i < MAX_FRAMES / 2; i += 256)
            tw[i] = (511u << 16) | 511u;
    }

    // ---- load xs: x rows (expand blocks) or notepitch row (pitch block) ----
    if (cg < CGROUPS) {
        const float4* xsrc = (const float4*)(x + ((size_t)b * CC + (size_t)cg * G) * TT);
        float4* xdst = (float4*)xs;
        #pragma unroll
        for (int i = tid; i < G * TT / 4; i += 256) xdst[i] = xsrc[i];
    } else {
        const float4* psrc = (const float4*)(notepitch + b * TT);
        float4* pdst = (float4*)xs;
        #pragma unroll
        for (int i = tid; i < TT / 4; i += 256) pdst[i] = psrc[i];
    }

    // ---- inclusive scan of pair sums (256 threads cover 512 elements) ----
    const int pair = r0 + r1;
    int v = pair;
    #pragma unroll
    for (int o = 1; o < 32; o <<= 1) {
        int n = __shfl_up_sync(0xFFFFFFFFu, v, o);
        if (lane >= o) v += n;
    }
    if (lane == 31) wsum[wid] = v;
    __syncthreads();
    if (wid == 0 && lane < 8) {
        int s = wsum[lane];
        #pragma unroll
        for (int o = 1; o < 8; o <<= 1) {
            int n = __shfl_up_sync(0x000000FFu, s, o);
            if (lane >= o) s += n;
        }
        wsum[lane] = s;
    }
    __syncthreads();
    const int base = (wid > 0) ? wsum[wid - 1] : 0;
    const int pair_incl = base + v;            // cum over pairs, inclusive
    const int e0_start  = pair_incl - pair;    // exclusive prefix of e0
    if (tid == 255) L_s = pair_incl;           // total frame length
    __syncthreads();

    // ---- scatter-fill tok map: tok[p] = e for p in [start_e, end_e) ----
    const int e0 = 2 * tid, e1 = 2 * tid + 1;
    for (int p = e0_start; p < e0_start + r0; p++)
        tok_s[p] = (unsigned short)e0;
    for (int p = e0_start + r0; p < pair_incl; p++)
        tok_s[p] = (unsigned short)e1;
    __syncthreads();

    const int L = L_s;

    if (cg == CGROUPS) {
        // ---- pitch + frame_lengths ----
        if (tid == 0) out[LEN_OFF + b] = (float)L;
        float* pout = out + PITCH_OFF + (size_t)b * MAX_FRAMES;
        for (int i = tid; i < MAX_FRAMES / 4; i += 256) {
            const int pos = i << 2;
            const uint2 tw = ((const uint2*)tok_s)[i];
            const int t0 = tw.x & 0xFFFF, t1 = tw.x >> 16;
            const int t2 = tw.y & 0xFFFF, t3 = tw.y >> 16;
            float4 v4;
            v4.x = (pos + 0 < L) ? (float)(int)xs[t0] : 0.0f;
            v4.y = (pos + 1 < L) ? (float)(int)xs[t1] : 0.0f;
            v4.z = (pos + 2 < L) ? (float)(int)xs[t2] : 0.0f;
            v4.w = (pos + 3 < L) ? (float)(int)xs[t3] : 0.0f;
            ((float4*)pout)[i] = v4;
        }
        return;
    }

    // ---- expand: 4 channels, float4 coalesced stores ----
    float* outbase = out + ((size_t)b * CC + (size_t)cg * G) * MAX_FRAMES;

    for (int i = tid; i < MAX_FRAMES / 4; i += 256) {   // 1664 float4 slots
        const int pos = i << 2;
        const uint2 tw = ((const uint2*)tok_s)[i];
        const int t0 = tw.x & 0xFFFF, t1 = tw.x >> 16;
        const int t2 = tw.y & 0xFFFF, t3 = tw.y >> 16;

        if (pos + 3 < L) {
            #pragma unroll
            for (int c = 0; c < G; c++) {
                const float* xc = xs + c * TT;
                float4 v4 = make_float4(xc[t0], xc[t1], xc[t2], xc[t3]);
                ((float4*)(outbase + (size_t)c * MAX_FRAMES))[i] = v4;
            }
        } else if (pos >= L) {
            const float4 z = make_float4(0.0f, 0.0f, 0.0f, 0.0f);
            #pragma unroll
            for (int c = 0; c < G; c++)
                ((float4*)(outbase + (size_t)c * MAX_FRAMES))[i] = z;
        } else {
            #pragma unroll
            for (int c = 0; c < G; c++) {
                const float* xc = xs + c * TT;
                float4 v4;
                v4.x = (pos + 0 < L) ? xc[t0] : 0.0f;
                v4.y = (pos + 1 < L) ? xc[t1] : 0.0f;
                v4.z = (pos + 2 < L) ? xc[t2] : 0.0f;
                v4.w = (pos + 3 < L) ? xc[t3] : 0.0f;
                ((float4*)(outbase + (size_t)c * MAX_FRAMES))[i] = v4;
            }
        }
    }
}

extern "C" void kernel_launch(void* const* d_in, const int* in_sizes, int n_in,
                              void* d_out, int out_size)
{
    const float* x         = (const float*)d_in[0];
    const float* notepitch = (const float*)d_in[1];
    const float* duration  = (const float*)d_in[2];
    // d_in[3] = x_lengths (unused by the reference)
    float* out = (float*)d_out;

    fused_kernel<<<dim3(CGROUPS + 1, BB), 256>>>(x, notepitch, duration, out);
}

// round 10
// speedup vs baseline: 1.1342x; 1.0468x over previous
#include <cuda_runtime.h>
#include <cuda_bf16.h>
#include <cstdint>

#define BB 32
#define CC 384
#define TT 512
#define MAX_FRAMES 6656   // TT * 13
#define G 8               // channels per expand block
#define CGROUPS (CC / G)  // 48

// out layout in d_out (float):
//   [0, BB*CC*MAX_FRAMES)            : out (b, c, pos)
//   [+0, +BB*MAX_FRAMES)             : pitch (b, pos)
//   [+0, +BB)                        : frame_lengths (as float value)
#define OUT_ELEMS   ((size_t)BB * CC * MAX_FRAMES)
#define PITCH_OFF   OUT_ELEMS
#define LEN_OFF     (OUT_ELEMS + (size_t)BB * MAX_FRAMES)

// ---------------------------------------------------------------------------
// Single fused kernel. grid = (CGROUPS+1, BB), 256 threads.
//   cg <  CGROUPS : expand G channels of x
//   cg == CGROUPS : write pitch + frame_lengths
// Every block independently recomputes the per-batch repeat counts, an
// inclusive scan (registers + shfl), and scatter-fills the tok map in SMEM.
// Output stores use streaming (.cs) hints — output is never re-read.
// ---------------------------------------------------------------------------
__global__ void __launch_bounds__(256) fused_kernel(
    const float* __restrict__ x,
    const float* __restrict__ notepitch,
    const float* __restrict__ duration,
    float* __restrict__ out)
{
    const int cg  = blockIdx.x;
    const int b   = blockIdx.y;
    const int tid = threadIdx.x;
    const int lane = tid & 31, wid = tid >> 5;

    __shared__ float xs[G * TT];                     // 16 KB (x rows OR pitch row)
    __shared__ unsigned short tok_s[MAX_FRAMES];     // 13 KB
    __shared__ int wsum[8];
    __shared__ int L_s;

    // ---- repeat counts for elements e0=2*tid, e1=2*tid+1 (exact fp32) ----
    const float2 d2 = ((const float2*)(duration + b * TT))[tid];
    int r0, r1;
    {
        const float fm = __fsub_rn(__fmul_rn(44100.0f, d2.x), 1024.0f);
        float rr;
        if (fm > 0.0f) rr = fmaxf(__fmul_rn(fm, (1.0f / 256.0f)), 1.0f);
        else           rr = (d2.x == 0.0f) ? 0.0f : 1.0f;
        r0 = (int)rr;
    }
    {
        const float fm = __fsub_rn(__fmul_rn(44100.0f, d2.y), 1024.0f);
        float rr;
        if (fm > 0.0f) rr = fmaxf(__fmul_rn(fm, (1.0f / 256.0f)), 1.0f);
        else           rr = (d2.y == 0.0f) ? 0.0f : 1.0f;
        r1 = (int)rr;
    }

    // ---- init tok map to 511 (searchsorted clamp value for pos >= L) ----
    {
        unsigned int* tw = (unsigned int*)tok_s;
        #pragma unroll
        for (int i = tid; i < MAX_FRAMES / 2; i += 256)
            tw[i] = (511u << 16) | 511u;
    }

    // ---- load xs: x rows (expand blocks) or notepitch row (pitch block) ----
    if (cg < CGROUPS) {
        const float4* xsrc = (const float4*)(x + ((size_t)b * CC + (size_t)cg * G) * TT);
        float4* xdst = (float4*)xs;
        #pragma unroll
        for (int i = tid; i < G * TT / 4; i += 256) xdst[i] = xsrc[i];
    } else {
        const float4* psrc = (const float4*)(notepitch + b * TT);
        float4* pdst = (float4*)xs;
        #pragma unroll
        for (int i = tid; i < TT / 4; i += 256) pdst[i] = psrc[i];
    }

    // ---- inclusive scan of pair sums (256 threads cover 512 elements) ----
    const int pair = r0 + r1;
    int v = pair;
    #pragma unroll
    for (int o = 1; o < 32; o <<= 1) {
        int n = __shfl_up_sync(0xFFFFFFFFu, v, o);
        if (lane >= o) v += n;
    }
    if (lane == 31) wsum[wid] = v;
    __syncthreads();
    if (wid == 0 && lane < 8) {
        int s = wsum[lane];
        #pragma unroll
        for (int o = 1; o < 8; o <<= 1) {
            int n = __shfl_up_sync(0x000000FFu, s, o);
            if (lane >= o) s += n;
        }
        wsum[lane] = s;
    }
    __syncthreads();
    const int base = (wid > 0) ? wsum[wid - 1] : 0;
    const int pair_incl = base + v;            // cum over pairs, inclusive
    const int e0_start  = pair_incl - pair;    // exclusive prefix of e0
    if (tid == 255) L_s = pair_incl;           // total frame length
    __syncthreads();

    // ---- scatter-fill tok map: tok[p] = e for p in [start_e, end_e) ----
    const int e0 = 2 * tid, e1 = 2 * tid + 1;
    for (int p = e0_start; p < e0_start + r0; p++)
        tok_s[p] = (unsigned short)e0;
    for (int p = e0_start + r0; p < pair_incl; p++)
        tok_s[p] = (unsigned short)e1;
    __syncthreads();

    const int L = L_s;

    if (cg == CGROUPS) {
        // ---- pitch + frame_lengths ----
        if (tid == 0) out[LEN_OFF + b] = (float)L;
        float4* pout = (float4*)(out + PITCH_OFF + (size_t)b * MAX_FRAMES);
        for (int i = tid; i < MAX_FRAMES / 4; i += 256) {
            const int pos = i << 2;
            const uint2 tw = ((const uint2*)tok_s)[i];
            const int t0 = tw.x & 0xFFFF, t1 = tw.x >> 16;
            const int t2 = tw.y & 0xFFFF, t3 = tw.y >> 16;
            float4 v4;
            v4.x = (pos + 0 < L) ? (float)(int)xs[t0] : 0.0f;
            v4.y = (pos + 1 < L) ? (float)(int)xs[t1] : 0.0f;
            v4.z = (pos + 2 < L) ? (float)(int)xs[t2] : 0.0f;
            v4.w = (pos + 3 < L) ? (float)(int)xs[t3] : 0.0f;
            __stcs(pout + i, v4);
        }
        return;
    }

    // ---- expand: G channels, float4 streaming stores ----
    float* outbase = out + ((size_t)b * CC + (size_t)cg * G) * MAX_FRAMES;

    for (int i = tid; i < MAX_FRAMES / 4; i += 256) {   // 1664 float4 slots
        const int pos = i << 2;
        const uint2 tw = ((const uint2*)tok_s)[i];
        const int t0 = tw.x & 0xFFFF, t1 = tw.x >> 16;
        const int t2 = tw.y & 0xFFFF, t3 = tw.y >> 16;

        if (pos + 3 < L) {
            #pragma unroll
            for (int c = 0; c < G; c++) {
                const float* xc = xs + c * TT;
                float4 v4 = make_float4(xc[t0], xc[t1], xc[t2], xc[t3]);
                __stcs((float4*)(outbase + (size_t)c * MAX_FRAMES) + i, v4);
            }
        } else if (pos >= L) {
            const float4 z = make_float4(0.0f, 0.0f, 0.0f, 0.0f);
            #pragma unroll
            for (int c = 0; c < G; c++)
                __stcs((float4*)(outbase + (size_t)c * MAX_FRAMES) + i, z);
        } else {
            #pragma unroll
            for (int c = 0; c < G; c++) {
                const float* xc = xs + c * TT;
                float4 v4;
                v4.x = (pos + 0 < L) ? xc[t0] : 0.0f;
                v4.y = (pos + 1 < L) ? xc[t1] : 0.0f;
                v4.z = (pos + 2 < L) ? xc[t2] : 0.0f;
                v4.w = (pos + 3 < L) ? xc[t3] : 0.0f;
                __stcs((float4*)(outbase + (size_t)c * MAX_FRAMES) + i, v4);
            }
        }
    }
}

extern "C" void kernel_launch(void* const* d_in, const int* in_sizes, int n_in,
                              void* d_out, int out_size)
{
    const float* x         = (const float*)d_in[0];
    const float* notepitch = (const float*)d_in[1];
    const float* duration  = (const float*)d_in[2];
    // d_in[3] = x_lengths (unused by the reference)
    float* out = (float*)d_out;

    fused_kernel<<<dim3(CGROUPS + 1, BB), 256>>>(x, notepitch, duration, out);
}

// round 11
// speedup vs baseline: 1.1781x; 1.0388x over previous
#include <cuda_runtime.h>
#include <cuda_bf16.h>
#include <cstdint>

#define BB 32
#define CC 384
#define TT 512
#define MAX_FRAMES 6656   // TT * 13
#define G 4               // channels per expand block
#define CGROUPS (CC / G)  // 96

// out layout in d_out (float):
//   [0, BB*CC*MAX_FRAMES)            : out (b, c, pos)
//   [+0, +BB*MAX_FRAMES)             : pitch (b, pos)
//   [+0, +BB)                        : frame_lengths (as float value)
#define OUT_ELEMS   ((size_t)BB * CC * MAX_FRAMES)
#define PITCH_OFF   OUT_ELEMS
#define LEN_OFF     (OUT_ELEMS + (size_t)BB * MAX_FRAMES)

// ---------------------------------------------------------------------------
// Single fused kernel. grid = (CGROUPS+1, BB), 256 threads.
//   cg <  CGROUPS : expand G channels of x
//   cg == CGROUPS : write pitch + frame_lengths
// Every block independently recomputes the per-batch repeat counts, an
// inclusive scan (registers + shfl), and scatter-fills the tok map in SMEM.
// Output stores use streaming (.cs) hints — output is never re-read.
// ---------------------------------------------------------------------------
__global__ void __launch_bounds__(256) fused_kernel(
    const float* __restrict__ x,
    const float* __restrict__ notepitch,
    const float* __restrict__ duration,
    float* __restrict__ out)
{
    const int cg  = blockIdx.x;
    const int b   = blockIdx.y;
    const int tid = threadIdx.x;
    const int lane = tid & 31, wid = tid >> 5;

    __shared__ float xs[G * TT];                     // 8 KB (x rows OR pitch row)
    __shared__ unsigned short tok_s[MAX_FRAMES];     // 13 KB
    __shared__ int wsum[8];
    __shared__ int L_s;

    // ---- repeat counts for elements e0=2*tid, e1=2*tid+1 (exact fp32) ----
    const float2 d2 = ((const float2*)(duration + b * TT))[tid];
    int r0, r1;
    {
        const float fm = __fsub_rn(__fmul_rn(44100.0f, d2.x), 1024.0f);
        float rr;
        if (fm > 0.0f) rr = fmaxf(__fmul_rn(fm, (1.0f / 256.0f)), 1.0f);
        else           rr = (d2.x == 0.0f) ? 0.0f : 1.0f;
        r0 = (int)rr;
    }
    {
        const float fm = __fsub_rn(__fmul_rn(44100.0f, d2.y), 1024.0f);
        float rr;
        if (fm > 0.0f) rr = fmaxf(__fmul_rn(fm, (1.0f / 256.0f)), 1.0f);
        else           rr = (d2.y == 0.0f) ? 0.0f : 1.0f;
        r1 = (int)rr;
    }

    // ---- init tok map to 511 (searchsorted clamp value for pos >= L) ----
    {
        unsigned int* tw = (unsigned int*)tok_s;
        #pragma unroll
        for (int i = tid; i < MAX_FRAMES / 2; i += 256)
            tw[i] = (511u << 16) | 511u;
    }

    // ---- load xs: x rows (expand blocks) or notepitch row (pitch block) ----
    if (cg < CGROUPS) {
        const float4* xsrc = (const float4*)(x + ((size_t)b * CC + (size_t)cg * G) * TT);
        float4* xdst = (float4*)xs;
        #pragma unroll
        for (int i = tid; i < G * TT / 4; i += 256) xdst[i] = xsrc[i];
    } else {
        const float4* psrc = (const float4*)(notepitch + b * TT);
        float4* pdst = (float4*)xs;
        #pragma unroll
        for (int i = tid; i < TT / 4; i += 256) pdst[i] = psrc[i];
    }

    // ---- inclusive scan of pair sums (256 threads cover 512 elements) ----
    const int pair = r0 + r1;
    int v = pair;
    #pragma unroll
    for (int o = 1; o < 32; o <<= 1) {
        int n = __shfl_up_sync(0xFFFFFFFFu, v, o);
        if (lane >= o) v += n;
    }
    if (lane == 31) wsum[wid] = v;
    __syncthreads();
    if (wid == 0 && lane < 8) {
        int s = wsum[lane];
        #pragma unroll
        for (int o = 1; o < 8; o <<= 1) {
            int n = __shfl_up_sync(0x000000FFu, s, o);
            if (lane >= o) s += n;
        }
        wsum[lane] = s;
    }
    __syncthreads();
    const int base = (wid > 0) ? wsum[wid - 1] : 0;
    const int pair_incl = base + v;            // cum over pairs, inclusive
    const int e0_start  = pair_incl - pair;    // exclusive prefix of e0
    if (tid == 255) L_s = pair_incl;           // total frame length
    __syncthreads();

    // ---- scatter-fill tok map: tok[p] = e for p in [start_e, end_e) ----
    const int e0 = 2 * tid, e1 = 2 * tid + 1;
    for (int p = e0_start; p < e0_start + r0; p++)
        tok_s[p] = (unsigned short)e0;
    for (int p = e0_start + r0; p < pair_incl; p++)
        tok_s[p] = (unsigned short)e1;
    __syncthreads();

    const int L = L_s;

    if (cg == CGROUPS) {
        // ---- pitch + frame_lengths ----
        if (tid == 0) out[LEN_OFF + b] = (float)L;
        float4* pout = (float4*)(out + PITCH_OFF + (size_t)b * MAX_FRAMES);
        for (int i = tid; i < MAX_FRAMES / 4; i += 256) {
            const int pos = i << 2;
            const uint2 tw = ((const uint2*)tok_s)[i];
            const int t0 = tw.x & 0xFFFF, t1 = tw.x >> 16;
            const int t2 = tw.y & 0xFFFF, t3 = tw.y >> 16;
            float4 v4;
            v4.x = (pos + 0 < L) ? (float)(int)xs[t0] : 0.0f;
            v4.y = (pos + 1 < L) ? (float)(int)xs[t1] : 0.0f;
            v4.z = (pos + 2 < L) ? (float)(int)xs[t2] : 0.0f;
            v4.w = (pos + 3 < L) ? (float)(int)xs[t3] : 0.0f;
            __stcs(pout + i, v4);
        }
        return;
    }

    // ---- expand: G channels, float4 streaming stores ----
    float* outbase = out + ((size_t)b * CC + (size_t)cg * G) * MAX_FRAMES;

    for (int i = tid; i < MAX_FRAMES / 4; i += 256) {   // 1664 float4 slots
        const int pos = i << 2;
        const uint2 tw = ((const uint2*)tok_s)[i];
        const int t0 = tw.x & 0xFFFF, t1 = tw.x >> 16;
        const int t2 = tw.y & 0xFFFF, t3 = tw.y >> 16;

        if (pos + 3 < L) {
            #pragma unroll
            for (int c = 0; c < G; c++) {
                const float* xc = xs + c * TT;
                float4 v4 = make_float4(xc[t0], xc[t1], xc[t2], xc[t3]);
                __stcs((float4*)(outbase + (size_t)c * MAX_FRAMES) + i, v4);
            }
        } else if (pos >= L) {
            const float4 z = make_float4(0.0f, 0.0f, 0.0f, 0.0f);
            #pragma unroll
            for (int c = 0; c < G; c++)
                __stcs((float4*)(outbase + (size_t)c * MAX_FRAMES) + i, z);
        } else {
            #pragma unroll
            for (int c = 0; c < G; c++) {
                const float* xc = xs + c * TT;
                float4 v4;
                v4.x = (pos + 0 < L) ? xc[t0] : 0.0f;
                v4.y = (pos + 1 < L) ? xc[t1] : 0.0f;
                v4.z = (pos + 2 < L) ? xc[t2] : 0.0f;
                v4.w = (pos + 3 < L) ? xc[t3] : 0.0f;
                __stcs((float4*)(outbase + (size_t)c * MAX_FRAMES) + i, v4);
            }
        }
    }
}

extern "C" void kernel_launch(void* const* d_in, const int* in_sizes, int n_in,
                              void* d_out, int out_size)
{
    const float* x         = (const float*)d_in[0];
    const float* notepitch = (const float*)d_in[1];
    const float* duration  = (const float*)d_in[2];
    // d_in[3] = x_lengths (unused by the reference)
    float* out = (float*)d_out;

    fused_kernel<<<dim3(CGROUPS + 1, BB), 256>>>(x, notepitch, duration, out);
}